// round 4
// baseline (speedup 1.0000x reference)
#include <cuda_runtime.h>
#include <cuda_bf16.h>

// <Z_0> after RY·RX on all qubits + CNOT chain reduces analytically to the
// qubit-0 gate only (CNOTs preserve the q0 bit; gates on q1..q15 are
// block-unitary and preserve per-block norms):
//   A = ||u||^2 - ||v||^2,  S = sum(u * conj(v))   (u = top half, v = bottom)
//   <Z_0> = cos^2(t) * A - 2 sin(t) * (Re S + cos(t) * Im S)
//
// R3 (= R2 re-run after infra failure, hardened): warp-granular balanced
// mapping. 148 blocks x 1024 threads = 4736 warps = 128 rows x 37 warps,
// each warp owning a contiguous 222-float4 slice. Compile-time wpr/chunk for
// the B=128 case (no runtime div, fixed trip counts -> front-batched LDG.128).
// 37th-arriving warp per row combines slots in fixed order (deterministic)
// and resets the counter for graph replay.

#ifndef QN
#define QN 16
#endif
static constexpr int D     = 1 << QN;      // 65536
static constexpr int HALF  = D >> 1;       // 32768 floats per half-row
static constexpr int HALF4 = HALF >> 2;    // 8192 float4 per half-row
static constexpr int NT    = 1024;
static constexpr int NSM   = 148;
static constexpr int MAXW  = 8192;
static constexpr int MAXB  = 1024;

__device__ float    g_part[MAXW * 3];
__device__ unsigned g_cnt[MAXB];           // zero at load; reset each launch

__inline__ __device__ float warp_sum(float v) {
    #pragma unroll
    for (int o = 16; o > 0; o >>= 1)
        v += __shfl_down_sync(0xffffffffu, v, o);
    return v;
}

__device__ __forceinline__ void accum(const float4 a, const float4 b,
                                      const float4 c, const float4 d,
                                      float& A, float& P, float& Q) {
    A += (a.x*a.x + c.x*c.x) - (b.x*b.x + d.x*d.x);
    A += (a.y*a.y + c.y*c.y) - (b.y*b.y + d.y*d.y);
    A += (a.z*a.z + c.z*c.z) - (b.z*b.z + d.z*d.z);
    A += (a.w*a.w + c.w*c.w) - (b.w*b.w + d.w*d.w);
    P += a.x*b.x + c.x*d.x;
    P += a.y*b.y + c.y*d.y;
    P += a.z*b.z + c.z*d.z;
    P += a.w*b.w + c.w*d.w;
    Q += c.x*b.x - a.x*d.x;
    Q += c.y*b.y - a.y*d.y;
    Q += c.z*b.z - a.z*d.z;
    Q += c.w*b.w - a.w*d.w;
}

__device__ __forceinline__ void finish(int w, int row, int wpr,
                                       float A, float P, float Q,
                                       const float* __restrict__ thetas,
                                       float* __restrict__ out) {
    A = warp_sum(A);
    P = warp_sum(P);
    Q = warp_sum(Q);
    if ((threadIdx.x & 31) == 0) {
        float* slot = &g_part[w * 3];
        slot[0] = A; slot[1] = P; slot[2] = Q;
        __threadfence();
        const unsigned old = atomicAdd(&g_cnt[row], 1u);
        if (old == (unsigned)(wpr - 1)) {
            __threadfence();
            float fA = 0.f, fP = 0.f, fQ = 0.f;
            const float* p = &g_part[row * wpr * 3];
            for (int s = 0; s < wpr; ++s) {      // fixed order: deterministic
                fA += p[s * 3 + 0];
                fP += p[s * 3 + 1];
                fQ += p[s * 3 + 2];
            }
            const float t  = thetas[0];
            const float ct = cosf(t);
            const float st = sinf(t);
            out[row] = ct * ct * fA - 2.f * st * (fP + ct * fQ);
            atomicExch(&g_cnt[row], 0u);         // clean for next graph replay
        }
    }
}

// ---- Specialized path: B = 128 -> wpr = 37, chunk4 = 222 (compile-time) ----
static constexpr int WPR   = 37;
static constexpr int CHUNK = 222;          // ceil(8192 / 37)
static constexpr int FULL  = CHUNK / 32;   // 6 unguarded iterations
__global__ __launch_bounds__(NT, 1)
void zexp_kernel_b128(const float* __restrict__ re,
                      const float* __restrict__ im,
                      const float* __restrict__ thetas,
                      float* __restrict__ out)
{
    const int w = blockIdx.x * (NT / 32) + (threadIdx.x >> 5);
    if (w >= 128 * WPR) return;
    const int lane = threadIdx.x & 31;
    const int row  = w / WPR;              // compile-time const divisor
    const int sub  = w - row * WPR;

    const size_t base = (size_t)row * D;
    const int c0   = sub * CHUNK;
    const int cend = min(c0 + CHUNK, HALF4);

    const float4* __restrict__ ru = (const float4*)(re + base);
    const float4* __restrict__ rv = (const float4*)(re + base + HALF);
    const float4* __restrict__ iu = (const float4*)(im + base);
    const float4* __restrict__ iv = (const float4*)(im + base + HALF);

    float A = 0.f, P = 0.f, Q = 0.f;

    // 6 unguarded iterations: 24 independent LDG.128 per lane, front-batched.
    #pragma unroll
    for (int k = 0; k < FULL; ++k) {
        const int idx = c0 + lane + k * 32;
        accum(__ldcs(&ru[idx]), __ldcs(&rv[idx]),
              __ldcs(&iu[idx]), __ldcs(&iv[idx]), A, P, Q);
    }
    // guarded tail (30 lanes active for interior warps; fewer for the last)
    {
        const int idx = c0 + lane + FULL * 32;
        if (idx < cend)
            accum(__ldcs(&ru[idx]), __ldcs(&rv[idx]),
                  __ldcs(&iu[idx]), __ldcs(&iv[idx]), A, P, Q);
    }

    finish(w, row, WPR, A, P, Q, thetas, out);
}

// ---- Generic fallback for any B ----
__global__ __launch_bounds__(NT, 1)
void zexp_kernel_gen(const float* __restrict__ re,
                     const float* __restrict__ im,
                     const float* __restrict__ thetas,
                     float* __restrict__ out,
                     int B, int wpr, int chunk4)
{
    const int w = blockIdx.x * (NT / 32) + (threadIdx.x >> 5);
    if (w >= B * wpr) return;
    const int lane = threadIdx.x & 31;
    const int row  = w / wpr;
    const int sub  = w - row * wpr;

    const size_t base = (size_t)row * D;
    const int c0   = sub * chunk4;
    const int cend = min(c0 + chunk4, HALF4);

    const float4* __restrict__ ru = (const float4*)(re + base);
    const float4* __restrict__ rv = (const float4*)(re + base + HALF);
    const float4* __restrict__ iu = (const float4*)(im + base);
    const float4* __restrict__ iv = (const float4*)(im + base + HALF);

    float A = 0.f, P = 0.f, Q = 0.f;
    #pragma unroll 4
    for (int idx = c0 + lane; idx < cend; idx += 32)
        accum(__ldcs(&ru[idx]), __ldcs(&rv[idx]),
              __ldcs(&iu[idx]), __ldcs(&iv[idx]), A, P, Q);

    finish(w, row, wpr, A, P, Q, thetas, out);
}

extern "C" void kernel_launch(void* const* d_in, const int* in_sizes, int n_in,
                              void* d_out, int out_size)
{
    const float* re     = (const float*)d_in[0];  // states_re (B, 65536)
    const float* im     = (const float*)d_in[1];  // states_im (B, 65536)
    const float* thetas = (const float*)d_in[2];  // (16,)
    float* out = (float*)d_out;                   // (B,)

    const int B = in_sizes[0] / D;

    if (B == 128) {
        const int blocks = (128 * WPR + (NT / 32) - 1) / (NT / 32);  // 148
        zexp_kernel_b128<<<blocks, NT>>>(re, im, thetas, out);
    } else {
        int wpr = (NSM * (NT / 32)) / (B > 0 ? B : 1);
        if (wpr < 1) wpr = 1;
        if (B * wpr > MAXW) wpr = MAXW / B;
        const int chunk4 = (HALF4 + wpr - 1) / wpr;
        const int blocks = (B * wpr + (NT / 32) - 1) / (NT / 32);
        zexp_kernel_gen<<<blocks, NT>>>(re, im, thetas, out, B, wpr, chunk4);
    }
}